// round 4
// baseline (speedup 1.0000x reference)
#include <cuda_runtime.h>
#include <cuda_fp16.h>
#include <cstdint>

// Problem dims (fixed by the dataset)
#define NNODES 10000
#define IND    256
#define HID    512
#define OUTD   256
#define KCAT   1024   // A||B concatenated width per node

// ---------------- scratch (no allocations allowed) ----------------
__device__ __half g_x16[NNODES * IND];                 // x in fp16
__device__ __half g_W1catT[KCAT * IND];                // [1024 n][256 k]  K-major
__device__ __half g_W2T[OUTD * HID];                   // [256 n][512 k]   K-major
__device__ __half g_AB[(size_t)NNODES * KCAT];         // per-node A||B, fp16
__device__ int    g_is64;                              // edge_index dtype flag

// ---------------- PTX helpers ----------------
__device__ __forceinline__ uint32_t smem_u32(const void* p) {
    return (uint32_t)__cvta_generic_to_shared(p);
}
__device__ __forceinline__ void ldsm_x4(uint32_t* r, uint32_t addr) {
    asm volatile("ldmatrix.sync.aligned.m8n8.x4.shared.b16 {%0,%1,%2,%3}, [%4];\n"
                 : "=r"(r[0]), "=r"(r[1]), "=r"(r[2]), "=r"(r[3]) : "r"(addr));
}
__device__ __forceinline__ void ldsm_x2(uint32_t* r, uint32_t addr) {
    asm volatile("ldmatrix.sync.aligned.m8n8.x2.shared.b16 {%0,%1}, [%2];\n"
                 : "=r"(r[0]), "=r"(r[1]) : "r"(addr));
}
__device__ __forceinline__ void mma16816(float* d, const uint32_t* a, const uint32_t* b) {
    asm volatile("mma.sync.aligned.m16n8k16.row.col.f32.f16.f16.f32 "
                 "{%0,%1,%2,%3}, {%4,%5,%6,%7}, {%8,%9}, {%0,%1,%2,%3};\n"
                 : "+f"(d[0]), "+f"(d[1]), "+f"(d[2]), "+f"(d[3])
                 : "r"(a[0]), "r"(a[1]), "r"(a[2]), "r"(a[3]), "r"(b[0]), "r"(b[1]));
}

// ---------------- prep: fp16 converts + transposes ----------------
__global__ void prep_kernel(const float* __restrict__ x,
                            const float* __restrict__ W1,
                            const float* __restrict__ W2) {
    int i = blockIdx.x * blockDim.x + threadIdx.x;
    if (i < NNODES * IND) g_x16[i] = __float2half(x[i]);
    if (i < KCAT * IND) {
        int j = i / IND, k = i % IND;
        // W1 is [512 rows][512 cols] row-major; rows 0..255 multiply x[s], 256..511 multiply x[t]
        float v = (j < HID) ? W1[(size_t)k * HID + j]
                            : W1[(size_t)(IND + k) * HID + (j - HID)];
        g_W1catT[i] = __float2half(v);     // g_W1catT[j*IND + k]
    }
    if (i < OUTD * HID) {
        int n = i / HID, k = i % HID;
        g_W2T[i] = __float2half(W2[(size_t)k * OUTD + n]);  // g_W2T[n*HID + k]
    }
}

// ---------------- detect edge_index dtype (int64 vs int32) ----------------
// If int64 (values < 10000): every odd 32-bit word in the first n_elem words is 0.
__global__ void detect_kernel(const int* __restrict__ w, int n_words) {
    __shared__ int nz;
    if (threadIdx.x == 0) nz = 0;
    __syncthreads();
    for (int i = threadIdx.x * 2 + 1; i < n_words; i += 2 * blockDim.x) {
        if (w[i] != 0) { nz = 1; break; }
        if (nz) break;
    }
    __syncthreads();
    if (threadIdx.x == 0) g_is64 = (nz == 0) ? 1 : 0;
}

// ---------------- GEMM1: g_AB = x16 @ W1cat  (M=10000, N=1024, K=256) ----------------
__global__ __launch_bounds__(256) void pre_gemm() {
    __shared__ __half sA[128 * 64];
    __shared__ __half sB[128 * 64];
    int tid = threadIdx.x;
    int mBase = blockIdx.x * 128;
    int nBase = blockIdx.y * 128;
    int wid = tid >> 5, lane = tid & 31;
    int wm = (wid & 3) * 32, wn = (wid >> 2) * 64;

    float acc[2][8][4];
#pragma unroll
    for (int a = 0; a < 2; a++)
#pragma unroll
        for (int b = 0; b < 8; b++)
#pragma unroll
            for (int c = 0; c < 4; c++) acc[a][b][c] = 0.f;

    for (int kc = 0; kc < IND; kc += 64) {
#pragma unroll
        for (int job = tid; job < 128 * 8; job += 256) {
            int r = job >> 3, v = job & 7;
            int m = mBase + r;
            uint4 val = make_uint4(0, 0, 0, 0);
            if (m < NNODES)
                val = *(const uint4*)(g_x16 + (size_t)m * IND + kc + (v << 3));
            *(uint4*)&sA[r * 64 + ((v ^ (r & 7)) << 3)] = val;
        }
#pragma unroll
        for (int job = tid; job < 128 * 8; job += 256) {
            int r = job >> 3, v = job & 7;
            *(uint4*)&sB[r * 64 + ((v ^ (r & 7)) << 3)] =
                *(const uint4*)(g_W1catT + (size_t)(nBase + r) * IND + kc + (v << 3));
        }
        __syncthreads();
#pragma unroll
        for (int kf = 0; kf < 64; kf += 16) {
            uint32_t a[2][4];
#pragma unroll
            for (int mf = 0; mf < 2; mf++) {
                int rr = wm + mf * 16 + (lane & 15);
                int gl = (kf >> 3) + (lane >> 4);
                ldsm_x4(a[mf], smem_u32(&sA[rr * 64 + ((gl ^ (rr & 7)) << 3)]));
            }
#pragma unroll
            for (int nf = 0; nf < 8; nf++) {
                int rr = wn + nf * 8 + (lane & 7);
                int gl = (kf >> 3) + ((lane >> 3) & 1);
                uint32_t b[2];
                ldsm_x2(b, smem_u32(&sB[rr * 64 + ((gl ^ (rr & 7)) << 3)]));
                mma16816(acc[0][nf], a[0], b);
                mma16816(acc[1][nf], a[1], b);
            }
        }
        __syncthreads();
    }
    // epilogue: fp32 acc -> fp16 AB table
    int g = lane >> 2, c2 = (lane & 3) << 1;
#pragma unroll
    for (int mf = 0; mf < 2; mf++)
#pragma unroll
        for (int nf = 0; nf < 8; nf++) {
            int n0 = nBase + wn + nf * 8 + c2;
            int m0 = mBase + wm + mf * 16 + g;
            if (m0 < NNODES)
                *(half2*)(g_AB + (size_t)m0 * KCAT + n0) =
                    __floats2half2_rn(acc[mf][nf][0], acc[mf][nf][1]);
            if (m0 + 8 < NNODES)
                *(half2*)(g_AB + (size_t)(m0 + 8) * KCAT + n0) =
                    __floats2half2_rn(acc[mf][nf][2], acc[mf][nf][3]);
        }
}

// ---------------- GEMM2: out = relu(A[s]+B[t]+b1) @ W2 + b2 ----------------
// M = E (128/CTA), N = 256 (128/CTA), K = 512
__global__ __launch_bounds__(256) void edge_gemm(const void* __restrict__ ei_raw,
                                                 const float* __restrict__ b1,
                                                 const float* __restrict__ b2,
                                                 float* __restrict__ out, int E) {
    __shared__ __half sA[128 * 64];
    __shared__ __half sB[128 * 64];
    __shared__ int sS[128], sT[128];
    __shared__ float sb1[HID];
    int tid = threadIdx.x;
    int eBase = blockIdx.x * 128;
    int nBase = blockIdx.y * 128;

    if (tid < 128) {
        int e = eBase + tid;
        int s = 0, t = 0;
        if (e < E) {
            if (g_is64) {
                const long long* ei = (const long long*)ei_raw;
                s = (int)ei[e];
                t = (int)ei[(size_t)E + e];
            } else {
                const int* ei = (const int*)ei_raw;
                s = ei[e];
                t = ei[E + e];
            }
        }
        s = min(max(s, 0), NNODES - 1);
        t = min(max(t, 0), NNODES - 1);
        sS[tid] = s;
        sT[tid] = t;
    }
    for (int i = tid; i < HID; i += 256) sb1[i] = b1[i];
    __syncthreads();

    int wid = tid >> 5, lane = tid & 31;
    int wm = (wid & 3) * 32, wn = (wid >> 2) * 64;

    float acc[2][8][4];
#pragma unroll
    for (int a = 0; a < 2; a++)
#pragma unroll
        for (int b = 0; b < 8; b++)
#pragma unroll
            for (int c = 0; c < 4; c++) acc[a][b][c] = 0.f;

    for (int kc = 0; kc < HID; kc += 64) {
        // build h chunk: gather + add + bias + relu + cvt fp16, swizzled smem
#pragma unroll
        for (int job = tid; job < 128 * 8; job += 256) {
            int r = job >> 3, v = job & 7;
            int k = kc + (v << 3);
            uint4 ua = *(const uint4*)(g_AB + (size_t)sS[r] * KCAT + k);
            uint4 ub = *(const uint4*)(g_AB + (size_t)sT[r] * KCAT + HID + k);
            const __half* ha = (const __half*)&ua;
            const __half* hb = (const __half*)&ub;
            __half res[8];
#pragma unroll
            for (int j = 0; j < 8; j++) {
                float f = __half2float(ha[j]) + __half2float(hb[j]) + sb1[k + j];
                res[j] = __float2half(fmaxf(f, 0.f));
            }
            *(uint4*)&sA[r * 64 + ((v ^ (r & 7)) << 3)] = *(uint4*)res;
        }
        // W2^T chunk
#pragma unroll
        for (int job = tid; job < 128 * 8; job += 256) {
            int r = job >> 3, v = job & 7;
            *(uint4*)&sB[r * 64 + ((v ^ (r & 7)) << 3)] =
                *(const uint4*)(g_W2T + (size_t)(nBase + r) * HID + kc + (v << 3));
        }
        __syncthreads();
#pragma unroll
        for (int kf = 0; kf < 64; kf += 16) {
            uint32_t a[2][4];
#pragma unroll
            for (int mf = 0; mf < 2; mf++) {
                int rr = wm + mf * 16 + (lane & 15);
                int gl = (kf >> 3) + (lane >> 4);
                ldsm_x4(a[mf], smem_u32(&sA[rr * 64 + ((gl ^ (rr & 7)) << 3)]));
            }
#pragma unroll
            for (int nf = 0; nf < 8; nf++) {
                int rr = wn + nf * 8 + (lane & 7);
                int gl = (kf >> 3) + ((lane >> 3) & 1);
                uint32_t b[2];
                ldsm_x2(b, smem_u32(&sB[rr * 64 + ((gl ^ (rr & 7)) << 3)]));
                mma16816(acc[0][nf], a[0], b);
                mma16816(acc[1][nf], a[1], b);
            }
        }
        __syncthreads();
    }

    // epilogue: + b2, fp32 out
    int g = lane >> 2, c2 = (lane & 3) << 1;
#pragma unroll
    for (int mf = 0; mf < 2; mf++)
#pragma unroll
        for (int nf = 0; nf < 8; nf++) {
            int n0 = nBase + wn + nf * 8 + c2;
            int e0 = eBase + wm + mf * 16 + g;
            float bx = b2[n0], by = b2[n0 + 1];
            if (e0 < E) {
                float2 o = make_float2(acc[mf][nf][0] + bx, acc[mf][nf][1] + by);
                *(float2*)(out + (size_t)e0 * OUTD + n0) = o;
            }
            if (e0 + 8 < E) {
                float2 o = make_float2(acc[mf][nf][2] + bx, acc[mf][nf][3] + by);
                *(float2*)(out + (size_t)(e0 + 8) * OUTD + n0) = o;
            }
        }
}

// ---------------- launch ----------------
extern "C" void kernel_launch(void* const* d_in, const int* in_sizes, int n_in,
                              void* d_out, int out_size) {
    const float* x  = (const float*)d_in[0];
    const void*  ei = d_in[1];
    const float* W1 = (const float*)d_in[2];
    const float* b1 = (const float*)d_in[3];
    const float* W2 = (const float*)d_in[4];
    const float* b2 = (const float*)d_in[5];
    int E = in_sizes[1] / 2;

    detect_kernel<<<1, 256>>>((const int*)ei, in_sizes[1]);
    prep_kernel<<<(NNODES * IND + 255) / 256, 256>>>(x, W1, W2);
    pre_gemm<<<dim3((NNODES + 127) / 128, KCAT / 128), 256>>>();
    edge_gemm<<<dim3((E + 127) / 128, OUTD / 128), 256>>>(ei, b1, b2, (float*)d_out, E);
}

// round 6
// speedup vs baseline: 1.1678x; 1.1678x over previous
#include <cuda_runtime.h>
#include <cuda_fp16.h>
#include <cstdint>

// Problem dims (fixed by the dataset)
#define NNODES 10000
#define IND    256
#define HID    512
#define OUTD   256
#define KCAT   1024   // A||B concatenated width per node

// ---------------- scratch (no allocations allowed) ----------------
__device__ __half g_x16[NNODES * IND];                 // x in fp16
__device__ __half g_W1catT[KCAT * IND];                // [1024 n][256 k]  K-major
__device__ __half g_W2T[OUTD * HID];                   // [256 n][512 k]   K-major
__device__ __half g_AB[(size_t)NNODES * KCAT];         // per-node A||B, fp16
__device__ int    g_is64;                              // edge_index dtype flag

// ---------------- PTX helpers ----------------
__device__ __forceinline__ uint32_t smem_u32(const void* p) {
    return (uint32_t)__cvta_generic_to_shared(p);
}
__device__ __forceinline__ void ldsm_x4(uint32_t* r, uint32_t addr) {
    asm volatile("ldmatrix.sync.aligned.m8n8.x4.shared.b16 {%0,%1,%2,%3}, [%4];\n"
                 : "=r"(r[0]), "=r"(r[1]), "=r"(r[2]), "=r"(r[3]) : "r"(addr));
}
__device__ __forceinline__ void ldsm_x2(uint32_t* r, uint32_t addr) {
    asm volatile("ldmatrix.sync.aligned.m8n8.x2.shared.b16 {%0,%1}, [%2];\n"
                 : "=r"(r[0]), "=r"(r[1]) : "r"(addr));
}
__device__ __forceinline__ void mma16816(float* d, const uint32_t* a, const uint32_t* b) {
    asm volatile("mma.sync.aligned.m16n8k16.row.col.f32.f16.f16.f32 "
                 "{%0,%1,%2,%3}, {%4,%5,%6,%7}, {%8,%9}, {%0,%1,%2,%3};\n"
                 : "+f"(d[0]), "+f"(d[1]), "+f"(d[2]), "+f"(d[3])
                 : "r"(a[0]), "r"(a[1]), "r"(a[2]), "r"(a[3]), "r"(b[0]), "r"(b[1]));
}
__device__ __forceinline__ void cp_async16(uint32_t smem_addr, const void* gptr) {
    asm volatile("cp.async.ca.shared.global [%0], [%1], 16;\n"
                 :: "r"(smem_addr), "l"(gptr) : "memory");
}
__device__ __forceinline__ void cp_commit() {
    asm volatile("cp.async.commit_group;\n" ::: "memory");
}
__device__ __forceinline__ void cp_wait_all() {
    asm volatile("cp.async.wait_group 0;\n" ::: "memory");
}

// ---------------- prep: fp16 converts + transposes ----------------
__global__ void prep_kernel(const float* __restrict__ x,
                            const float* __restrict__ W1,
                            const float* __restrict__ W2) {
    int i = blockIdx.x * blockDim.x + threadIdx.x;
    if (i < NNODES * IND) g_x16[i] = __float2half(x[i]);
    if (i < KCAT * IND) {
        int j = i / IND, k = i % IND;
        float v = (j < HID) ? W1[(size_t)k * HID + j]
                            : W1[(size_t)(IND + k) * HID + (j - HID)];
        g_W1catT[i] = __float2half(v);
    }
    if (i < OUTD * HID) {
        int n = i / HID, k = i % HID;
        g_W2T[i] = __float2half(W2[(size_t)k * OUTD + n]);
    }
}

// ---------------- detect edge_index dtype (int64 vs int32) ----------------
__global__ void detect_kernel(const int* __restrict__ w, int n_words) {
    __shared__ int nz;
    if (threadIdx.x == 0) nz = 0;
    __syncthreads();
    for (int i = threadIdx.x * 2 + 1; i < n_words; i += 2 * blockDim.x) {
        if (w[i] != 0) { nz = 1; break; }
        if (nz) break;
    }
    __syncthreads();
    if (threadIdx.x == 0) g_is64 = (nz == 0) ? 1 : 0;
}

// ---------------- GEMM1: g_AB = x16 @ W1cat  (M=10000, N=1024, K=256) ----------------
__global__ __launch_bounds__(256) void pre_gemm() {
    __shared__ __half sA[128 * 64];
    __shared__ __half sB[128 * 64];
    int tid = threadIdx.x;
    int mBase = blockIdx.x * 128;
    int nBase = blockIdx.y * 128;
    int wid = tid >> 5, lane = tid & 31;
    int wm = (wid & 3) * 32, wn = (wid >> 2) * 64;

    float acc[2][8][4];
#pragma unroll
    for (int a = 0; a < 2; a++)
#pragma unroll
        for (int b = 0; b < 8; b++)
#pragma unroll
            for (int c = 0; c < 4; c++) acc[a][b][c] = 0.f;

    for (int kc = 0; kc < IND; kc += 64) {
#pragma unroll
        for (int job = tid; job < 128 * 8; job += 256) {
            int r = job >> 3, v = job & 7;
            int m = mBase + r;
            uint4 val = make_uint4(0, 0, 0, 0);
            if (m < NNODES)
                val = *(const uint4*)(g_x16 + (size_t)m * IND + kc + (v << 3));
            *(uint4*)&sA[r * 64 + ((v ^ (r & 7)) << 3)] = val;
        }
#pragma unroll
        for (int job = tid; job < 128 * 8; job += 256) {
            int r = job >> 3, v = job & 7;
            *(uint4*)&sB[r * 64 + ((v ^ (r & 7)) << 3)] =
                *(const uint4*)(g_W1catT + (size_t)(nBase + r) * IND + kc + (v << 3));
        }
        __syncthreads();
#pragma unroll
        for (int kf = 0; kf < 64; kf += 16) {
            uint32_t a[2][4];
#pragma unroll
            for (int mf = 0; mf < 2; mf++) {
                int rr = wm + mf * 16 + (lane & 15);
                int gl = (kf >> 3) + (lane >> 4);
                ldsm_x4(a[mf], smem_u32(&sA[rr * 64 + ((gl ^ (rr & 7)) << 3)]));
            }
#pragma unroll
            for (int nf = 0; nf < 8; nf++) {
                int rr = wn + nf * 8 + (lane & 7);
                int gl = (kf >> 3) + ((lane >> 3) & 1);
                uint32_t b[2];
                ldsm_x2(b, smem_u32(&sB[rr * 64 + ((gl ^ (rr & 7)) << 3)]));
                mma16816(acc[0][nf], a[0], b);
                mma16816(acc[1][nf], a[1], b);
            }
        }
        __syncthreads();
    }
    int g = lane >> 2, c2 = (lane & 3) << 1;
#pragma unroll
    for (int mf = 0; mf < 2; mf++)
#pragma unroll
        for (int nf = 0; nf < 8; nf++) {
            int n0 = nBase + wn + nf * 8 + c2;
            int m0 = mBase + wm + mf * 16 + g;
            if (m0 < NNODES)
                *(half2*)(g_AB + (size_t)m0 * KCAT + n0) =
                    __floats2half2_rn(acc[mf][nf][0], acc[mf][nf][1]);
            if (m0 + 8 < NNODES)
                *(half2*)(g_AB + (size_t)(m0 + 8) * KCAT + n0) =
                    __floats2half2_rn(acc[mf][nf][2], acc[mf][nf][3]);
        }
}

// ---------------- GEMM2: out = relu(A[s]+B[t]+b1) @ W2 + b2 ----------------
// CTA tile: 128 edges x 256 out (FULL N -> single h build), K=512 in 8 chunks of 64.
// 512 threads, warp grid 4(m) x 4(n), warp tile 32m x 64n.
// Double-buffered smem stages, ONE __syncthreads per chunk, cp.async for W2 tile,
// gather loads for next chunk issued before the mma loop (latency hidden under HMMA).

// dynamic smem layout (bytes):
#define EG_SS       0                      // int[128]
#define EG_ST       512                    // int[128]
#define EG_SB2      1024                   // float[256]
#define EG_SB1      2048                   // float[512]
#define EG_STAGE0   4096                   // A(16384) + B(32768) = 49152 per stage
#define EG_STAGE_SZ 49152
#define EG_B_OFF    16384
#define EG_SMEM_TOTAL (EG_STAGE0 + 2 * EG_STAGE_SZ)   // 102400

__global__ __launch_bounds__(512, 1) void edge_gemm2(const void* __restrict__ ei_raw,
                                                     const float* __restrict__ b1,
                                                     const float* __restrict__ b2,
                                                     float* __restrict__ out, int E) {
    extern __shared__ char smem[];
    uint32_t smem_base = smem_u32(smem);
    int tid = threadIdx.x;
    int wid = tid >> 5, lane = tid & 31;
    int eBase = blockIdx.x * 128;

    int* sS = (int*)(smem + EG_SS);
    int* sT = (int*)(smem + EG_ST);
    float* sb2 = (float*)(smem + EG_SB2);
    float* sb1 = (float*)(smem + EG_SB1);

    // ---- indices + biases ----
    if (tid < 128) {
        int e = eBase + tid;
        int s = 0, t = 0;
        if (e < E) {
            if (g_is64) {
                const long long* ei = (const long long*)ei_raw;
                s = (int)ei[e];
                t = (int)ei[(size_t)E + e];
            } else {
                const int* ei = (const int*)ei_raw;
                s = ei[e];
                t = ei[E + e];
            }
        }
        sS[tid] = min(max(s, 0), NNODES - 1);
        sT[tid] = min(max(t, 0), NNODES - 1);
    }
    if (tid < 256) sb2[tid] = b2[tid];
    if (tid < 512) sb1[tid] = b1[tid];
    __syncthreads();

    // per-thread fixed job coords (2 A-build jobs, 4 B cp.async jobs)
    const int ar0 = tid >> 3;              // 0..63
    const int ar1 = ar0 + 64;              // 64..127
    const int av  = tid & 7;               // 16B group in 128B row
    const int s0 = sS[ar0], t0 = sT[ar0];
    const int s1 = sS[ar1], t1 = sT[ar1];
    const uint32_t aw0 = smem_base + EG_STAGE0 + ar0 * 128 + ((av ^ (ar0 & 7)) << 4);
    const uint32_t aw1 = smem_base + EG_STAGE0 + ar1 * 128 + ((av ^ (ar1 & 7)) << 4);

    int wm = (wid & 3) * 32, wn = (wid >> 2) * 64;

    float acc[2][8][4];
#pragma unroll
    for (int a = 0; a < 2; a++)
#pragma unroll
        for (int b = 0; b < 8; b++)
#pragma unroll
            for (int c = 0; c < 4; c++) acc[a][b][c] = 0.f;

    // ---- prologue: chunk 0 into stage 0 ----
    {
        int k = av << 3;   // kc = 0
        uint4 ua = *(const uint4*)(g_AB + (size_t)s0 * KCAT + k);
        uint4 ub = *(const uint4*)(g_AB + (size_t)t0 * KCAT + HID + k);
        uint4 uc = *(const uint4*)(g_AB + (size_t)s1 * KCAT + k);
        uint4 ud = *(const uint4*)(g_AB + (size_t)t1 * KCAT + HID + k);
        __half r0[8], r1[8];
        const __half* ha = (const __half*)&ua; const __half* hb = (const __half*)&ub;
        const __half* hc = (const __half*)&uc; const __half* hd = (const __half*)&ud;
#pragma unroll
        for (int j = 0; j < 8; j++) {
            float f0 = __half2float(ha[j]) + __half2float(hb[j]) + sb1[k + j];
            float f1 = __half2float(hc[j]) + __half2float(hd[j]) + sb1[k + j];
            r0[j] = __float2half(fmaxf(f0, 0.f));
            r1[j] = __float2half(fmaxf(f1, 0.f));
        }
        *(uint4*)(smem + EG_STAGE0 + ar0 * 128 + ((av ^ (ar0 & 7)) << 4)) = *(uint4*)r0;
        *(uint4*)(smem + EG_STAGE0 + ar1 * 128 + ((av ^ (ar1 & 7)) << 4)) = *(uint4*)r1;
        // B chunk 0 via cp.async: 4 jobs
#pragma unroll
        for (int j = 0; j < 4; j++) {
            int job = tid + j * 512;          // 0..2047
            int r = job >> 3, v = job & 7;
            cp_async16(smem_base + EG_STAGE0 + EG_B_OFF + r * 128 + ((v ^ (r & 7)) << 4),
                       g_W2T + (size_t)r * HID + (v << 3));
        }
        cp_commit();
    }

    // ---- mainloop ----
#pragma unroll 1
    for (int ch = 0; ch < 8; ch++) {
        int st = ch & 1;
        cp_wait_all();
        __syncthreads();                          // stage st ready; stage st^1 free
        char* curA = smem + EG_STAGE0 + st * EG_STAGE_SZ;
        char* curB = curA + EG_B_OFF;

        uint4 ua, ub, uc, ud;
        int kn = 0;
        if (ch < 7) {
            // B(ch+1) via cp.async into other stage
            int kc1 = (ch + 1) * 64;
            uint32_t nb = smem_base + EG_STAGE0 + (st ^ 1) * EG_STAGE_SZ + EG_B_OFF;
#pragma unroll
            for (int j = 0; j < 4; j++) {
                int job = tid + j * 512;
                int r = job >> 3, v = job & 7;
                cp_async16(nb + r * 128 + ((v ^ (r & 7)) << 4),
                           g_W2T + (size_t)r * HID + kc1 + (v << 3));
            }
            cp_commit();
            // gather loads for A(ch+1) — in flight under the mma loop below
            kn = kc1 + (av << 3);
            ua = *(const uint4*)(g_AB + (size_t)s0 * KCAT + kn);
            ub = *(const uint4*)(g_AB + (size_t)t0 * KCAT + HID + kn);
            uc = *(const uint4*)(g_AB + (size_t)s1 * KCAT + kn);
            ud = *(const uint4*)(g_AB + (size_t)t1 * KCAT + HID + kn);
        }

        // ---- HMMA on stage st ----
        __half* sA16 = (__half*)curA;
        __half* sB16 = (__half*)curB;
#pragma unroll
        for (int kf = 0; kf < 64; kf += 16) {
            uint32_t a[2][4];
#pragma unroll
            for (int mf = 0; mf < 2; mf++) {
                int rr = wm + mf * 16 + (lane & 15);
                int gl = (kf >> 3) + (lane >> 4);
                ldsm_x4(a[mf], smem_u32(&sA16[rr * 64 + ((gl ^ (rr & 7)) << 3)]));
            }
#pragma unroll
            for (int nf = 0; nf < 8; nf++) {
                int rr = wn + nf * 8 + (lane & 7);
                int gl = (kf >> 3) + ((lane >> 3) & 1);
                uint32_t b[2];
                ldsm_x2(b, smem_u32(&sB16[rr * 64 + ((gl ^ (rr & 7)) << 3)]));
                mma16816(acc[0][nf], a[0], b);
                mma16816(acc[1][nf], a[1], b);
            }
        }

        if (ch < 7) {
            // finish A(ch+1): relu + cvt + store to other stage
            uint32_t nbA = (st ^ 1) * EG_STAGE_SZ;
            __half r0[8], r1[8];
            const __half* ha = (const __half*)&ua; const __half* hb = (const __half*)&ub;
            const __half* hc = (const __half*)&uc; const __half* hd = (const __half*)&ud;
#pragma unroll
            for (int j = 0; j < 8; j++) {
                float f0 = __half2float(ha[j]) + __half2float(hb[j]) + sb1[kn + j];
                float f1 = __half2float(hc[j]) + __half2float(hd[j]) + sb1[kn + j];
                r0[j] = __float2half(fmaxf(f0, 0.f));
                r1[j] = __float2half(fmaxf(f1, 0.f));
            }
            *(uint4*)((char*)smem + (aw0 - smem_base) + nbA) = *(uint4*)r0;
            *(uint4*)((char*)smem + (aw1 - smem_base) + nbA) = *(uint4*)r1;
        }
    }

    // ---- epilogue: + b2, fp32 out ----
    int g = lane >> 2, c2 = (lane & 3) << 1;
#pragma unroll
    for (int mf = 0; mf < 2; mf++) {
        int e0 = eBase + wm + mf * 16 + g;
#pragma unroll
        for (int nf = 0; nf < 8; nf++) {
            int n0 = wn + nf * 8 + c2;
            float bx = sb2[n0], by = sb2[n0 + 1];
            if (e0 < E) {
                float2 o = make_float2(acc[mf][nf][0] + bx, acc[mf][nf][1] + by);
                *(float2*)(out + (size_t)e0 * OUTD + n0) = o;
            }
            if (e0 + 8 < E) {
                float2 o = make_float2(acc[mf][nf][2] + bx, acc[mf][nf][3] + by);
                *(float2*)(out + (size_t)(e0 + 8) * OUTD + n0) = o;
            }
        }
    }
}

// ---------------- launch ----------------
extern "C" void kernel_launch(void* const* d_in, const int* in_sizes, int n_in,
                              void* d_out, int out_size) {
    const float* x  = (const float*)d_in[0];
    const void*  ei = d_in[1];
    const float* W1 = (const float*)d_in[2];
    const float* b1 = (const float*)d_in[3];
    const float* W2 = (const float*)d_in[4];
    const float* b2 = (const float*)d_in[5];
    int E = in_sizes[1] / 2;

    cudaFuncSetAttribute(edge_gemm2, cudaFuncAttributeMaxDynamicSharedMemorySize,
                         EG_SMEM_TOTAL);

    detect_kernel<<<1, 256>>>((const int*)ei, in_sizes[1]);
    prep_kernel<<<(NNODES * IND + 255) / 256, 256>>>(x, W1, W2);
    pre_gemm<<<dim3((NNODES + 127) / 128, KCAT / 128), 256>>>();
    edge_gemm2<<<(E + 127) / 128, 512, EG_SMEM_TOTAL>>>(ei, b1, b2, (float*)d_out, E);
}

// round 7
// speedup vs baseline: 1.1740x; 1.0053x over previous
#include <cuda_runtime.h>
#include <cuda_fp16.h>
#include <cstdint>

// Problem dims (fixed by the dataset)
#define NNODES 10000
#define IND    256
#define HID    512
#define OUTD   256
#define KCAT   1024   // A||B concatenated width per node

// ---------------- scratch (no allocations allowed) ----------------
__device__ __half g_x16[NNODES * IND];                 // x in fp16
__device__ __half g_W1catT[KCAT * IND];                // [1024 n][256 k]  K-major
__device__ __half g_W2T[OUTD * HID];                   // [256 n][512 k]   K-major
__device__ __half g_AB[(size_t)NNODES * KCAT];         // per-node A||B, fp16
__device__ int    g_is64;                              // edge_index dtype flag

// ---------------- PTX helpers ----------------
__device__ __forceinline__ uint32_t smem_u32(const void* p) {
    return (uint32_t)__cvta_generic_to_shared(p);
}
__device__ __forceinline__ void ldsm_x4(uint32_t* r, uint32_t addr) {
    asm volatile("ldmatrix.sync.aligned.m8n8.x4.shared.b16 {%0,%1,%2,%3}, [%4];\n"
                 : "=r"(r[0]), "=r"(r[1]), "=r"(r[2]), "=r"(r[3]) : "r"(addr));
}
__device__ __forceinline__ void ldsm_x2(uint32_t* r, uint32_t addr) {
    asm volatile("ldmatrix.sync.aligned.m8n8.x2.shared.b16 {%0,%1}, [%2];\n"
                 : "=r"(r[0]), "=r"(r[1]) : "r"(addr));
}
__device__ __forceinline__ void mma16816(float* d, const uint32_t* a, const uint32_t* b) {
    asm volatile("mma.sync.aligned.m16n8k16.row.col.f32.f16.f16.f32 "
                 "{%0,%1,%2,%3}, {%4,%5,%6,%7}, {%8,%9}, {%0,%1,%2,%3};\n"
                 : "+f"(d[0]), "+f"(d[1]), "+f"(d[2]), "+f"(d[3])
                 : "r"(a[0]), "r"(a[1]), "r"(a[2]), "r"(a[3]), "r"(b[0]), "r"(b[1]));
}
__device__ __forceinline__ void cp_async16(uint32_t smem_addr, const void* gptr) {
    asm volatile("cp.async.ca.shared.global [%0], [%1], 16;\n"
                 :: "r"(smem_addr), "l"(gptr) : "memory");
}
__device__ __forceinline__ void cp_commit() {
    asm volatile("cp.async.commit_group;\n" ::: "memory");
}
__device__ __forceinline__ void cp_wait_all() {
    asm volatile("cp.async.wait_group 0;\n" ::: "memory");
}

// ---------------- prep: fp16 converts + transposes ----------------
__global__ void prep_kernel(const float* __restrict__ x,
                            const float* __restrict__ W1,
                            const float* __restrict__ W2) {
    int i = blockIdx.x * blockDim.x + threadIdx.x;
    if (i < NNODES * IND) g_x16[i] = __float2half(x[i]);
    if (i < KCAT * IND) {
        int j = i / IND, k = i % IND;
        float v = (j < HID) ? W1[(size_t)k * HID + j]
                            : W1[(size_t)(IND + k) * HID + (j - HID)];
        g_W1catT[i] = __float2half(v);
    }
    if (i < OUTD * HID) {
        int n = i / HID, k = i % HID;
        g_W2T[i] = __float2half(W2[(size_t)k * OUTD + n]);
    }
}

// ---------------- detect edge_index dtype (int64 vs int32) ----------------
__global__ void detect_kernel(const int* __restrict__ w, int n_words) {
    __shared__ int nz;
    if (threadIdx.x == 0) nz = 0;
    __syncthreads();
    for (int i = threadIdx.x * 2 + 1; i < n_words; i += 2 * blockDim.x) {
        if (w[i] != 0) { nz = 1; break; }
        if (nz) break;
    }
    __syncthreads();
    if (threadIdx.x == 0) g_is64 = (nz == 0) ? 1 : 0;
}

// ---------------- GEMM1: g_AB = x16 @ W1cat  (M=10000, N=1024, K=256) ----------------
__global__ __launch_bounds__(256) void pre_gemm() {
    __shared__ __half sA[128 * 64];
    __shared__ __half sB[128 * 64];
    int tid = threadIdx.x;
    int mBase = blockIdx.x * 128;
    int nBase = blockIdx.y * 128;
    int wid = tid >> 5, lane = tid & 31;
    int wm = (wid & 3) * 32, wn = (wid >> 2) * 64;

    float acc[2][8][4];
#pragma unroll
    for (int a = 0; a < 2; a++)
#pragma unroll
        for (int b = 0; b < 8; b++)
#pragma unroll
            for (int c = 0; c < 4; c++) acc[a][b][c] = 0.f;

    for (int kc = 0; kc < IND; kc += 64) {
#pragma unroll
        for (int job = tid; job < 128 * 8; job += 256) {
            int r = job >> 3, v = job & 7;
            int m = mBase + r;
            uint4 val = make_uint4(0, 0, 0, 0);
            if (m < NNODES)
                val = *(const uint4*)(g_x16 + (size_t)m * IND + kc + (v << 3));
            *(uint4*)&sA[r * 64 + ((v ^ (r & 7)) << 3)] = val;
        }
#pragma unroll
        for (int job = tid; job < 128 * 8; job += 256) {
            int r = job >> 3, v = job & 7;
            *(uint4*)&sB[r * 64 + ((v ^ (r & 7)) << 3)] =
                *(const uint4*)(g_W1catT + (size_t)(nBase + r) * IND + kc + (v << 3));
        }
        __syncthreads();
#pragma unroll
        for (int kf = 0; kf < 64; kf += 16) {
            uint32_t a[2][4];
#pragma unroll
            for (int mf = 0; mf < 2; mf++) {
                int rr = wm + mf * 16 + (lane & 15);
                int gl = (kf >> 3) + (lane >> 4);
                ldsm_x4(a[mf], smem_u32(&sA[rr * 64 + ((gl ^ (rr & 7)) << 3)]));
            }
#pragma unroll
            for (int nf = 0; nf < 8; nf++) {
                int rr = wn + nf * 8 + (lane & 7);
                int gl = (kf >> 3) + ((lane >> 3) & 1);
                uint32_t b[2];
                ldsm_x2(b, smem_u32(&sB[rr * 64 + ((gl ^ (rr & 7)) << 3)]));
                mma16816(acc[0][nf], a[0], b);
                mma16816(acc[1][nf], a[1], b);
            }
        }
        __syncthreads();
    }
    int g = lane >> 2, c2 = (lane & 3) << 1;
#pragma unroll
    for (int mf = 0; mf < 2; mf++)
#pragma unroll
        for (int nf = 0; nf < 8; nf++) {
            int n0 = nBase + wn + nf * 8 + c2;
            int m0 = mBase + wm + mf * 16 + g;
            if (m0 < NNODES)
                *(half2*)(g_AB + (size_t)m0 * KCAT + n0) =
                    __floats2half2_rn(acc[mf][nf][0], acc[mf][nf][1]);
            if (m0 + 8 < NNODES)
                *(half2*)(g_AB + (size_t)(m0 + 8) * KCAT + n0) =
                    __floats2half2_rn(acc[mf][nf][2], acc[mf][nf][3]);
        }
}

// ---------------- GEMM2: out = relu(A[s]+B[t]+b1) @ W2 + b2 ----------------
// CTA tile: 128 edges x 256 out, K=512 in 8 chunks of 64.
// 256 threads, warp grid 2(m) x 4(n), warp tile 64m x 64n (acc 128 regs/thread).
// Double-buffered stages, one __syncthreads per chunk, cp.async W2, gather
// prefetch in registers spanning the mma loop.

// dynamic smem layout (bytes):
#define EG_SS       0                      // int[128]
#define EG_ST       512                    // int[128]
#define EG_SB2      1024                   // float[256]
#define EG_SB1      2048                   // float[512]
#define EG_STAGE0   4096                   // A(16384) + B(32768) = 49152 per stage
#define EG_STAGE_SZ 49152
#define EG_B_OFF    16384
#define EG_SMEM_TOTAL (EG_STAGE0 + 2 * EG_STAGE_SZ)   // 102400

__global__ __launch_bounds__(256, 1) void edge_gemm3(const void* __restrict__ ei_raw,
                                                     const float* __restrict__ b1,
                                                     const float* __restrict__ b2,
                                                     float* __restrict__ out, int E) {
    extern __shared__ char smem[];
    uint32_t smem_base = smem_u32(smem);
    int tid = threadIdx.x;
    int wid = tid >> 5, lane = tid & 31;
    int eBase = blockIdx.x * 128;

    int* sS = (int*)(smem + EG_SS);
    int* sT = (int*)(smem + EG_ST);
    float* sb2 = (float*)(smem + EG_SB2);
    float* sb1 = (float*)(smem + EG_SB1);

    // ---- indices + biases ----
    if (tid < 128) {
        int e = eBase + tid;
        int s = 0, t = 0;
        if (e < E) {
            if (g_is64) {
                const long long* ei = (const long long*)ei_raw;
                s = (int)ei[e];
                t = (int)ei[(size_t)E + e];
            } else {
                const int* ei = (const int*)ei_raw;
                s = ei[e];
                t = ei[E + e];
            }
        }
        sS[tid] = min(max(s, 0), NNODES - 1);
        sT[tid] = min(max(t, 0), NNODES - 1);
    }
    if (tid < 256) { sb2[tid] = b2[tid]; }
    sb1[tid] = b1[tid];
    sb1[tid + 256] = b1[tid + 256];
    __syncthreads();

    // per-thread A-build job coords: 4 jobs (rows tid>>3 + {0,32,64,96}), group av
    const int av = tid & 7;
    int jS[4], jT[4];
    uint32_t awoff[4];
#pragma unroll
    for (int it = 0; it < 4; it++) {
        int r = (tid >> 3) + it * 32;
        jS[it] = sS[r];
        jT[it] = sT[r];
        awoff[it] = (uint32_t)(r * 128 + ((av ^ (r & 7)) << 4));
    }

    const int wm = (wid & 1) * 64;        // 2 m-warps
    const int wn = (wid >> 1) * 64;       // 4 n-warps

    float acc[4][8][4];
#pragma unroll
    for (int a = 0; a < 4; a++)
#pragma unroll
        for (int b = 0; b < 8; b++)
#pragma unroll
            for (int c = 0; c < 4; c++) acc[a][b][c] = 0.f;

    // ---- prologue: chunk 0 into stage 0 ----
    {
        int k = av << 3;
#pragma unroll
        for (int it = 0; it < 4; it++) {
            uint4 ua = *(const uint4*)(g_AB + (size_t)jS[it] * KCAT + k);
            uint4 ub = *(const uint4*)(g_AB + (size_t)jT[it] * KCAT + HID + k);
            const __half* ha = (const __half*)&ua;
            const __half* hb = (const __half*)&ub;
            __half res[8];
#pragma unroll
            for (int j = 0; j < 8; j++) {
                float f = __half2float(ha[j]) + __half2float(hb[j]) + sb1[k + j];
                res[j] = __float2half(fmaxf(f, 0.f));
            }
            *(uint4*)(smem + EG_STAGE0 + awoff[it]) = *(uint4*)res;
        }
#pragma unroll
        for (int jj = 0; jj < 8; jj++) {
            int job = tid + jj * 256;          // 0..2047
            int r = job >> 3, v = job & 7;
            cp_async16(smem_base + EG_STAGE0 + EG_B_OFF + r * 128 + ((v ^ (r & 7)) << 4),
                       g_W2T + (size_t)r * HID + (v << 3));
        }
        cp_commit();
    }

    // ---- mainloop ----
#pragma unroll 1
    for (int ch = 0; ch < 8; ch++) {
        int st = ch & 1;
        cp_wait_all();
        __syncthreads();                          // stage st ready; stage st^1 free
        char* curA = smem + EG_STAGE0 + st * EG_STAGE_SZ;
        char* curB = curA + EG_B_OFF;

        uint4 pa[4], pb[4];
        int kn = 0;
        if (ch < 7) {
            int kc1 = (ch + 1) * 64;
            // B(ch+1) via cp.async into other stage
            uint32_t nb = smem_base + EG_STAGE0 + (st ^ 1) * EG_STAGE_SZ + EG_B_OFF;
#pragma unroll
            for (int jj = 0; jj < 8; jj++) {
                int job = tid + jj * 256;
                int r = job >> 3, v = job & 7;
                cp_async16(nb + r * 128 + ((v ^ (r & 7)) << 4),
                           g_W2T + (size_t)r * HID + kc1 + (v << 3));
            }
            cp_commit();
            // gather loads for A(ch+1) — in flight under the mma loop below
            kn = kc1 + (av << 3);
#pragma unroll
            for (int it = 0; it < 4; it++) {
                pa[it] = *(const uint4*)(g_AB + (size_t)jS[it] * KCAT + kn);
                pb[it] = *(const uint4*)(g_AB + (size_t)jT[it] * KCAT + HID + kn);
            }
        }

        // ---- HMMA on stage st: warp tile 64x64 ----
        __half* sA16 = (__half*)curA;
        __half* sB16 = (__half*)curB;
#pragma unroll
        for (int kf = 0; kf < 64; kf += 16) {
            uint32_t a[4][4];
#pragma unroll
            for (int mf = 0; mf < 4; mf++) {
                int rr = wm + mf * 16 + (lane & 15);
                int gl = (kf >> 3) + (lane >> 4);
                ldsm_x4(a[mf], smem_u32(&sA16[rr * 64 + ((gl ^ (rr & 7)) << 3)]));
            }
#pragma unroll
            for (int nf2 = 0; nf2 < 4; nf2++) {
                int rr = wn + nf2 * 16 + ((lane >> 4) << 3) + (lane & 7);
                int gl = (kf >> 3) + ((lane >> 3) & 1);
                uint32_t b[4];
                ldsm_x4(b, smem_u32(&sB16[rr * 64 + ((gl ^ (rr & 7)) << 3)]));
#pragma unroll
                for (int mf = 0; mf < 4; mf++) {
                    mma16816(acc[mf][2 * nf2],     a[mf], b);
                    mma16816(acc[mf][2 * nf2 + 1], a[mf], b + 2);
                }
            }
        }

        if (ch < 7) {
            // finish A(ch+1): relu + cvt + store to other stage
            char* nA = smem + EG_STAGE0 + (st ^ 1) * EG_STAGE_SZ;
#pragma unroll
            for (int it = 0; it < 4; it++) {
                const __half* ha = (const __half*)&pa[it];
                const __half* hb = (const __half*)&pb[it];
                __half res[8];
#pragma unroll
                for (int j = 0; j < 8; j++) {
                    float f = __half2float(ha[j]) + __half2float(hb[j]) + sb1[kn + j];
                    res[j] = __float2half(fmaxf(f, 0.f));
                }
                *(uint4*)(nA + awoff[it]) = *(uint4*)res;
            }
        }
    }

    // ---- epilogue: + b2, fp32 out ----
    int g = lane >> 2, c2 = (lane & 3) << 1;
#pragma unroll
    for (int mf = 0; mf < 4; mf++) {
        int e0 = eBase + wm + mf * 16 + g;
#pragma unroll
        for (int nf = 0; nf < 8; nf++) {
            int n0 = wn + nf * 8 + c2;
            float bx = sb2[n0], by = sb2[n0 + 1];
            if (e0 < E) {
                float2 o = make_float2(acc[mf][nf][0] + bx, acc[mf][nf][1] + by);
                *(float2*)(out + (size_t)e0 * OUTD + n0) = o;
            }
            if (e0 + 8 < E) {
                float2 o = make_float2(acc[mf][nf][2] + bx, acc[mf][nf][3] + by);
                *(float2*)(out + (size_t)(e0 + 8) * OUTD + n0) = o;
            }
        }
    }
}

// ---------------- launch ----------------
extern "C" void kernel_launch(void* const* d_in, const int* in_sizes, int n_in,
                              void* d_out, int out_size) {
    const float* x  = (const float*)d_in[0];
    const void*  ei = d_in[1];
    const float* W1 = (const float*)d_in[2];
    const float* b1 = (const float*)d_in[3];
    const float* W2 = (const float*)d_in[4];
    const float* b2 = (const float*)d_in[5];
    int E = in_sizes[1] / 2;

    cudaFuncSetAttribute(edge_gemm3, cudaFuncAttributeMaxDynamicSharedMemorySize,
                         EG_SMEM_TOTAL);

    detect_kernel<<<1, 256>>>((const int*)ei, in_sizes[1]);
    prep_kernel<<<(NNODES * IND + 255) / 256, 256>>>(x, W1, W2);
    pre_gemm<<<dim3((NNODES + 127) / 128, KCAT / 128), 256>>>();
    edge_gemm3<<<(E + 127) / 128, 256, EG_SMEM_TOTAL>>>(ei, b1, b2, (float*)d_out, E);
}

// round 8
// speedup vs baseline: 1.1871x; 1.0112x over previous
#include <cuda_runtime.h>
#include <cuda_fp16.h>
#include <cstdint>

// Problem dims (fixed by the dataset)
#define NNODES 10000
#define IND    256
#define HID    512
#define OUTD   256
#define KCAT   1024   // A||B concatenated width per node

// ---------------- scratch (no allocations allowed) ----------------
__device__ __half g_x16[NNODES * IND];                 // x in fp16
__device__ __half g_W1catT[KCAT * IND];                // [1024 n][256 k]  K-major
__device__ __half g_W2T[OUTD * HID];                   // [256 n][512 k]   K-major
__device__ __half g_AB[(size_t)NNODES * KCAT];         // per-node A||B, fp16
__device__ int    g_is64;                              // edge_index dtype flag

// ---------------- PTX helpers ----------------
__device__ __forceinline__ uint32_t smem_u32(const void* p) {
    return (uint32_t)__cvta_generic_to_shared(p);
}
__device__ __forceinline__ void ldsm_x4(uint32_t* r, uint32_t addr) {
    asm volatile("ldmatrix.sync.aligned.m8n8.x4.shared.b16 {%0,%1,%2,%3}, [%4];\n"
                 : "=r"(r[0]), "=r"(r[1]), "=r"(r[2]), "=r"(r[3]) : "r"(addr));
}
__device__ __forceinline__ void ldsm_x2(uint32_t* r, uint32_t addr) {
    asm volatile("ldmatrix.sync.aligned.m8n8.x2.shared.b16 {%0,%1}, [%2];\n"
                 : "=r"(r[0]), "=r"(r[1]) : "r"(addr));
}
__device__ __forceinline__ void mma16816(float* d, const uint32_t* a, const uint32_t* b) {
    asm volatile("mma.sync.aligned.m16n8k16.row.col.f32.f16.f16.f32 "
                 "{%0,%1,%2,%3}, {%4,%5,%6,%7}, {%8,%9}, {%0,%1,%2,%3};\n"
                 : "+f"(d[0]), "+f"(d[1]), "+f"(d[2]), "+f"(d[3])
                 : "r"(a[0]), "r"(a[1]), "r"(a[2]), "r"(a[3]), "r"(b[0]), "r"(b[1]));
}
__device__ __forceinline__ void cp_async16(uint32_t smem_addr, const void* gptr) {
    asm volatile("cp.async.ca.shared.global [%0], [%1], 16;\n"
                 :: "r"(smem_addr), "l"(gptr) : "memory");
}
__device__ __forceinline__ void cp_commit() {
    asm volatile("cp.async.commit_group;\n" ::: "memory");
}
__device__ __forceinline__ void cp_wait_all() {
    asm volatile("cp.async.wait_group 0;\n" ::: "memory");
}

// ---------------- prep: fp16 converts + transposes ----------------
__global__ void prep_kernel(const float* __restrict__ x,
                            const float* __restrict__ W1,
                            const float* __restrict__ W2) {
    int i = blockIdx.x * blockDim.x + threadIdx.x;
    if (i < NNODES * IND) g_x16[i] = __float2half(x[i]);
    if (i < KCAT * IND) {
        int j = i / IND, k = i % IND;
        float v = (j < HID) ? W1[(size_t)k * HID + j]
                            : W1[(size_t)(IND + k) * HID + (j - HID)];
        g_W1catT[i] = __float2half(v);
    }
    if (i < OUTD * HID) {
        int n = i / HID, k = i % HID;
        g_W2T[i] = __float2half(W2[(size_t)k * OUTD + n]);
    }
}

// ---------------- detect edge_index dtype (int64 vs int32) ----------------
__global__ void detect_kernel(const int* __restrict__ w, int n_words) {
    __shared__ int nz;
    if (threadIdx.x == 0) nz = 0;
    __syncthreads();
    for (int i = threadIdx.x * 2 + 1; i < n_words; i += 2 * blockDim.x) {
        if (w[i] != 0) { nz = 1; break; }
        if (nz) break;
    }
    __syncthreads();
    if (threadIdx.x == 0) g_is64 = (nz == 0) ? 1 : 0;
}

// ---------------- GEMM1: g_AB = x16 @ W1cat  (M=10000, N=1024, K=256) ----------------
__global__ __launch_bounds__(256) void pre_gemm() {
    __shared__ __half sA[128 * 64];
    __shared__ __half sB[128 * 64];
    int tid = threadIdx.x;
    int mBase = blockIdx.x * 128;
    int nBase = blockIdx.y * 128;
    int wid = tid >> 5, lane = tid & 31;
    int wm = (wid & 3) * 32, wn = (wid >> 2) * 64;

    float acc[2][8][4];
#pragma unroll
    for (int a = 0; a < 2; a++)
#pragma unroll
        for (int b = 0; b < 8; b++)
#pragma unroll
            for (int c = 0; c < 4; c++) acc[a][b][c] = 0.f;

    for (int kc = 0; kc < IND; kc += 64) {
#pragma unroll
        for (int job = tid; job < 128 * 8; job += 256) {
            int r = job >> 3, v = job & 7;
            int m = mBase + r;
            uint4 val = make_uint4(0, 0, 0, 0);
            if (m < NNODES)
                val = *(const uint4*)(g_x16 + (size_t)m * IND + kc + (v << 3));
            *(uint4*)&sA[r * 64 + ((v ^ (r & 7)) << 3)] = val;
        }
#pragma unroll
        for (int job = tid; job < 128 * 8; job += 256) {
            int r = job >> 3, v = job & 7;
            *(uint4*)&sB[r * 64 + ((v ^ (r & 7)) << 3)] =
                *(const uint4*)(g_W1catT + (size_t)(nBase + r) * IND + kc + (v << 3));
        }
        __syncthreads();
#pragma unroll
        for (int kf = 0; kf < 64; kf += 16) {
            uint32_t a[2][4];
#pragma unroll
            for (int mf = 0; mf < 2; mf++) {
                int rr = wm + mf * 16 + (lane & 15);
                int gl = (kf >> 3) + (lane >> 4);
                ldsm_x4(a[mf], smem_u32(&sA[rr * 64 + ((gl ^ (rr & 7)) << 3)]));
            }
#pragma unroll
            for (int nf = 0; nf < 8; nf++) {
                int rr = wn + nf * 8 + (lane & 7);
                int gl = (kf >> 3) + ((lane >> 3) & 1);
                uint32_t b[2];
                ldsm_x2(b, smem_u32(&sB[rr * 64 + ((gl ^ (rr & 7)) << 3)]));
                mma16816(acc[0][nf], a[0], b);
                mma16816(acc[1][nf], a[1], b);
            }
        }
        __syncthreads();
    }
    int g = lane >> 2, c2 = (lane & 3) << 1;
#pragma unroll
    for (int mf = 0; mf < 2; mf++)
#pragma unroll
        for (int nf = 0; nf < 8; nf++) {
            int n0 = nBase + wn + nf * 8 + c2;
            int m0 = mBase + wm + mf * 16 + g;
            if (m0 < NNODES)
                *(half2*)(g_AB + (size_t)m0 * KCAT + n0) =
                    __floats2half2_rn(acc[mf][nf][0], acc[mf][nf][1]);
            if (m0 + 8 < NNODES)
                *(half2*)(g_AB + (size_t)(m0 + 8) * KCAT + n0) =
                    __floats2half2_rn(acc[mf][nf][2], acc[mf][nf][3]);
        }
}

// ---------------- GEMM2: out = relu(A[s]+B[t]+b1) @ W2 + b2 ----------------
// CTA tile: 64 edges x 256 out, K=512 in 8 chunks of 64.
// 128 threads, 4 warps: warp tile 64m x 64n (wn = wid*64). 2 CTAs per SM
// (128 thr x <=256 regs = half RF; smem 84KB x 2 <= 227KB) so one CTA's
// barrier/cp-wait bubbles are covered by the other CTA's HMMAs.

// dynamic smem layout (bytes):
#define EG_SS       0                      // int[64]
#define EG_ST       256                    // int[64]
#define EG_SB2      1024                   // float[256]
#define EG_SB1      2048                   // float[512]
#define EG_STAGE0   4096                   // A(8192) + B(32768) = 40960 per stage
#define EG_STAGE_SZ 40960
#define EG_B_OFF    8192
#define EG_SMEM_TOTAL (EG_STAGE0 + 2 * EG_STAGE_SZ)   // 86016

__global__ __launch_bounds__(128, 2) void edge_gemm4(const void* __restrict__ ei_raw,
                                                     const float* __restrict__ b1,
                                                     const float* __restrict__ b2,
                                                     float* __restrict__ out, int E) {
    extern __shared__ char smem[];
    uint32_t smem_base = smem_u32(smem);
    int tid = threadIdx.x;
    int wid = tid >> 5, lane = tid & 31;
    int eBase = blockIdx.x * 64;

    int* sS = (int*)(smem + EG_SS);
    int* sT = (int*)(smem + EG_ST);
    float* sb2 = (float*)(smem + EG_SB2);
    float* sb1 = (float*)(smem + EG_SB1);

    // ---- indices + biases ----
    if (tid < 64) {
        int e = eBase + tid;
        int s = 0, t = 0;
        if (e < E) {
            if (g_is64) {
                const long long* ei = (const long long*)ei_raw;
                s = (int)ei[e];
                t = (int)ei[(size_t)E + e];
            } else {
                const int* ei = (const int*)ei_raw;
                s = ei[e];
                t = ei[E + e];
            }
        }
        sS[tid] = min(max(s, 0), NNODES - 1);
        sT[tid] = min(max(t, 0), NNODES - 1);
    }
    sb2[tid] = b2[tid];
    sb2[tid + 128] = b2[tid + 128];
#pragma unroll
    for (int j = 0; j < 4; j++) sb1[tid + j * 128] = b1[tid + j * 128];
    __syncthreads();

    // per-thread A-build job coords: 4 jobs (rows tid>>3 + {0,16,32,48}), group av
    const int av = tid & 7;
    int jS[4], jT[4];
    uint32_t awoff[4];
#pragma unroll
    for (int it = 0; it < 4; it++) {
        int r = (tid >> 3) + it * 16;
        jS[it] = sS[r];
        jT[it] = sT[r];
        awoff[it] = (uint32_t)(r * 128 + ((av ^ (r & 7)) << 4));
    }

    const int wn = wid * 64;              // 4 n-warps, full 64-edge m per warp

    float acc[4][8][4];
#pragma unroll
    for (int a = 0; a < 4; a++)
#pragma unroll
        for (int b = 0; b < 8; b++)
#pragma unroll
            for (int c = 0; c < 4; c++) acc[a][b][c] = 0.f;

    // ---- prologue: chunk 0 into stage 0 ----
    {
        int k = av << 3;
#pragma unroll
        for (int it = 0; it < 4; it++) {
            uint4 ua = *(const uint4*)(g_AB + (size_t)jS[it] * KCAT + k);
            uint4 ub = *(const uint4*)(g_AB + (size_t)jT[it] * KCAT + HID + k);
            const __half* ha = (const __half*)&ua;
            const __half* hb = (const __half*)&ub;
            __half res[8];
#pragma unroll
            for (int j = 0; j < 8; j++) {
                float f = __half2float(ha[j]) + __half2float(hb[j]) + sb1[k + j];
                res[j] = __float2half(fmaxf(f, 0.f));
            }
            *(uint4*)(smem + EG_STAGE0 + awoff[it]) = *(uint4*)res;
        }
#pragma unroll
        for (int jj = 0; jj < 16; jj++) {
            int job = tid + jj * 128;          // 0..2047
            int r = job >> 3, v = job & 7;
            cp_async16(smem_base + EG_STAGE0 + EG_B_OFF + r * 128 + ((v ^ (r & 7)) << 4),
                       g_W2T + (size_t)r * HID + (v << 3));
        }
        cp_commit();
    }

    // ---- mainloop ----
#pragma unroll 1
    for (int ch = 0; ch < 8; ch++) {
        int st = ch & 1;
        cp_wait_all();
        __syncthreads();                          // stage st ready; stage st^1 free
        char* curA = smem + EG_STAGE0 + st * EG_STAGE_SZ;
        char* curB = curA + EG_B_OFF;

        uint4 pa[4], pb[4];
        int kn = 0;
        if (ch < 7) {
            int kc1 = (ch + 1) * 64;
            // B(ch+1) via cp.async into other stage
            uint32_t nb = smem_base + EG_STAGE0 + (st ^ 1) * EG_STAGE_SZ + EG_B_OFF;
#pragma unroll
            for (int jj = 0; jj < 16; jj++) {
                int job = tid + jj * 128;
                int r = job >> 3, v = job & 7;
                cp_async16(nb + r * 128 + ((v ^ (r & 7)) << 4),
                           g_W2T + (size_t)r * HID + kc1 + (v << 3));
            }
            cp_commit();
            // gather loads for A(ch+1) — in flight under the mma loop below
            kn = kc1 + (av << 3);
#pragma unroll
            for (int it = 0; it < 4; it++) {
                pa[it] = *(const uint4*)(g_AB + (size_t)jS[it] * KCAT + kn);
                pb[it] = *(const uint4*)(g_AB + (size_t)jT[it] * KCAT + HID + kn);
            }
        }

        // ---- HMMA on stage st: warp tile 64m x 64n ----
        __half* sA16 = (__half*)curA;
        __half* sB16 = (__half*)curB;
#pragma unroll
        for (int kf = 0; kf < 64; kf += 16) {
            uint32_t a[4][4];
#pragma unroll
            for (int mf = 0; mf < 4; mf++) {
                int rr = mf * 16 + (lane & 15);
                int gl = (kf >> 3) + (lane >> 4);
                ldsm_x4(a[mf], smem_u32(&sA16[rr * 64 + ((gl ^ (rr & 7)) << 3)]));
            }
#pragma unroll
            for (int nf2 = 0; nf2 < 4; nf2++) {
                int rr = wn + nf2 * 16 + ((lane >> 4) << 3) + (lane & 7);
                int gl = (kf >> 3) + ((lane >> 3) & 1);
                uint32_t b[4];
                ldsm_x4(b, smem_u32(&sB16[rr * 64 + ((gl ^ (rr & 7)) << 3)]));
#pragma unroll
                for (int mf = 0; mf < 4; mf++) {
                    mma16816(acc[mf][2 * nf2],     a[mf], b);
                    mma16816(acc[mf][2 * nf2 + 1], a[mf], b + 2);
                }
            }
        }

        if (ch < 7) {
            // finish A(ch+1): relu + cvt + store to other stage
            char* nA = smem + EG_STAGE0 + (st ^ 1) * EG_STAGE_SZ;
#pragma unroll
            for (int it = 0; it < 4; it++) {
                const __half* ha = (const __half*)&pa[it];
                const __half* hb = (const __half*)&pb[it];
                __half res[8];
#pragma unroll
                for (int j = 0; j < 8; j++) {
                    float f = __half2float(ha[j]) + __half2float(hb[j]) + sb1[kn + j];
                    res[j] = __float2half(fmaxf(f, 0.f));
                }
                *(uint4*)(nA + awoff[it]) = *(uint4*)res;
            }
        }
    }

    // ---- epilogue: + b2, fp32 out ----
    int g = lane >> 2, c2 = (lane & 3) << 1;
#pragma unroll
    for (int mf = 0; mf < 4; mf++) {
        int e0 = eBase + mf * 16 + g;
#pragma unroll
        for (int nf = 0; nf < 8; nf++) {
            int n0 = wn + nf * 8 + c2;
            float bx = sb2[n0], by = sb2[n0 + 1];
            if (e0 < E) {
                float2 o = make_float2(acc[mf][nf][0] + bx, acc[mf][nf][1] + by);
                *(float2*)(out + (size_t)e0 * OUTD + n0) = o;
            }
            if (e0 + 8 < E) {
                float2 o = make_float2(acc[mf][nf][2] + bx, acc[mf][nf][3] + by);
                *(float2*)(out + (size_t)(e0 + 8) * OUTD + n0) = o;
            }
        }
    }
}

// ---------------- launch ----------------
extern "C" void kernel_launch(void* const* d_in, const int* in_sizes, int n_in,
                              void* d_out, int out_size) {
    const float* x  = (const float*)d_in[0];
    const void*  ei = d_in[1];
    const float* W1 = (const float*)d_in[2];
    const float* b1 = (const float*)d_in[3];
    const float* W2 = (const float*)d_in[4];
    const float* b2 = (const float*)d_in[5];
    int E = in_sizes[1] / 2;

    cudaFuncSetAttribute(edge_gemm4, cudaFuncAttributeMaxDynamicSharedMemorySize,
                         EG_SMEM_TOTAL);

    detect_kernel<<<1, 256>>>((const int*)ei, in_sizes[1]);
    prep_kernel<<<(NNODES * IND + 255) / 256, 256>>>(x, W1, W2);
    pre_gemm<<<dim3((NNODES + 127) / 128, KCAT / 128), 256>>>();
    edge_gemm4<<<(E + 63) / 64, 128, EG_SMEM_TOTAL>>>(ei, b1, b2, (float*)d_out, E);
}

// round 10
// speedup vs baseline: 1.1935x; 1.0054x over previous
#include <cuda_runtime.h>
#include <cuda_fp16.h>
#include <cstdint>

// Problem dims (fixed by the dataset)
#define NNODES 10000
#define IND    256
#define HID    512
#define OUTD   256
#define KCAT   1024   // A||B concatenated width per node

// ---------------- scratch (no allocations allowed) ----------------
__device__ __half g_x16[NNODES * IND];                 // x in fp16
__device__ __half g_W1catT[KCAT * IND];                // [1024 n][256 k]  K-major
__device__ __half g_W2T[OUTD * HID];                   // [256 n][512 k]   K-major
__device__ __half g_AB[(size_t)NNODES * KCAT];         // per-node A||B, fp16
__device__ int    g_is64;                              // edge_index dtype flag

// ---------------- PTX helpers ----------------
__device__ __forceinline__ uint32_t smem_u32(const void* p) {
    return (uint32_t)__cvta_generic_to_shared(p);
}
__device__ __forceinline__ void ldsm_x4(uint32_t* r, uint32_t addr) {
    asm volatile("ldmatrix.sync.aligned.m8n8.x4.shared.b16 {%0,%1,%2,%3}, [%4];\n"
                 : "=r"(r[0]), "=r"(r[1]), "=r"(r[2]), "=r"(r[3]) : "r"(addr));
}
__device__ __forceinline__ void ldsm_x2(uint32_t* r, uint32_t addr) {
    asm volatile("ldmatrix.sync.aligned.m8n8.x2.shared.b16 {%0,%1}, [%2];\n"
                 : "=r"(r[0]), "=r"(r[1]) : "r"(addr));
}
__device__ __forceinline__ void mma16816(float* d, const uint32_t* a, const uint32_t* b) {
    asm volatile("mma.sync.aligned.m16n8k16.row.col.f32.f16.f16.f32 "
                 "{%0,%1,%2,%3}, {%4,%5,%6,%7}, {%8,%9}, {%0,%1,%2,%3};\n"
                 : "+f"(d[0]), "+f"(d[1]), "+f"(d[2]), "+f"(d[3])
                 : "r"(a[0]), "r"(a[1]), "r"(a[2]), "r"(a[3]), "r"(b[0]), "r"(b[1]));
}
__device__ __forceinline__ void cp_async16(uint32_t smem_addr, const void* gptr) {
    asm volatile("cp.async.ca.shared.global [%0], [%1], 16;\n"
                 :: "r"(smem_addr), "l"(gptr) : "memory");
}
__device__ __forceinline__ void cp_commit() {
    asm volatile("cp.async.commit_group;\n" ::: "memory");
}
__device__ __forceinline__ void cp_wait_all() {
    asm volatile("cp.async.wait_group 0;\n" ::: "memory");
}

// ---------------- prep: fp16 converts + transposes ----------------
__global__ void prep_kernel(const float* __restrict__ x,
                            const float* __restrict__ W1,
                            const float* __restrict__ W2) {
    int i = blockIdx.x * blockDim.x + threadIdx.x;
    if (i < NNODES * IND) g_x16[i] = __float2half(x[i]);
    if (i < KCAT * IND) {
        int j = i / IND, k = i % IND;
        float v = (j < HID) ? W1[(size_t)k * HID + j]
                            : W1[(size_t)(IND + k) * HID + (j - HID)];
        g_W1catT[i] = __float2half(v);
    }
    if (i < OUTD * HID) {
        int n = i / HID, k = i % HID;
        g_W2T[i] = __float2half(W2[(size_t)k * OUTD + n]);
    }
}

// ---------------- detect edge_index dtype (int64 vs int32) ----------------
__global__ void detect_kernel(const int* __restrict__ w, int n_words) {
    __shared__ int nz;
    if (threadIdx.x == 0) nz = 0;
    __syncthreads();
    for (int i = threadIdx.x * 2 + 1; i < n_words; i += 2 * blockDim.x) {
        if (w[i] != 0) { nz = 1; break; }
        if (nz) break;
    }
    __syncthreads();
    if (threadIdx.x == 0) g_is64 = (nz == 0) ? 1 : 0;
}

// ---------------- GEMM1: g_AB = x16 @ W1cat  (M=10000, N=1024, K=256) ----------------
__global__ __launch_bounds__(256) void pre_gemm() {
    __shared__ __half sA[128 * 64];
    __shared__ __half sB[128 * 64];
    int tid = threadIdx.x;
    int mBase = blockIdx.x * 128;
    int nBase = blockIdx.y * 128;
    int wid = tid >> 5, lane = tid & 31;
    int wm = (wid & 3) * 32, wn = (wid >> 2) * 64;

    float acc[2][8][4];
#pragma unroll
    for (int a = 0; a < 2; a++)
#pragma unroll
        for (int b = 0; b < 8; b++)
#pragma unroll
            for (int c = 0; c < 4; c++) acc[a][b][c] = 0.f;

    for (int kc = 0; kc < IND; kc += 64) {
#pragma unroll
        for (int job = tid; job < 128 * 8; job += 256) {
            int r = job >> 3, v = job & 7;
            int m = mBase + r;
            uint4 val = make_uint4(0, 0, 0, 0);
            if (m < NNODES)
                val = *(const uint4*)(g_x16 + (size_t)m * IND + kc + (v << 3));
            *(uint4*)&sA[r * 64 + ((v ^ (r & 7)) << 3)] = val;
        }
#pragma unroll
        for (int job = tid; job < 128 * 8; job += 256) {
            int r = job >> 3, v = job & 7;
            *(uint4*)&sB[r * 64 + ((v ^ (r & 7)) << 3)] =
                *(const uint4*)(g_W1catT + (size_t)(nBase + r) * IND + kc + (v << 3));
        }
        __syncthreads();
#pragma unroll
        for (int kf = 0; kf < 64; kf += 16) {
            uint32_t a[2][4];
#pragma unroll
            for (int mf = 0; mf < 2; mf++) {
                int rr = wm + mf * 16 + (lane & 15);
                int gl = (kf >> 3) + (lane >> 4);
                ldsm_x4(a[mf], smem_u32(&sA[rr * 64 + ((gl ^ (rr & 7)) << 3)]));
            }
#pragma unroll
            for (int nf = 0; nf < 8; nf++) {
                int rr = wn + nf * 8 + (lane & 7);
                int gl = (kf >> 3) + ((lane >> 3) & 1);
                uint32_t b[2];
                ldsm_x2(b, smem_u32(&sB[rr * 64 + ((gl ^ (rr & 7)) << 3)]));
                mma16816(acc[0][nf], a[0], b);
                mma16816(acc[1][nf], a[1], b);
            }
        }
        __syncthreads();
    }
    int g = lane >> 2, c2 = (lane & 3) << 1;
#pragma unroll
    for (int mf = 0; mf < 2; mf++)
#pragma unroll
        for (int nf = 0; nf < 8; nf++) {
            int n0 = nBase + wn + nf * 8 + c2;
            int m0 = mBase + wm + mf * 16 + g;
            if (m0 < NNODES)
                *(half2*)(g_AB + (size_t)m0 * KCAT + n0) =
                    __floats2half2_rn(acc[mf][nf][0], acc[mf][nf][1]);
            if (m0 + 8 < NNODES)
                *(half2*)(g_AB + (size_t)(m0 + 8) * KCAT + n0) =
                    __floats2half2_rn(acc[mf][nf][2], acc[mf][nf][3]);
        }
}

// ---------------- GEMM2: out = relu(A[s]+B[t]+b1) @ W2 + b2 ----------------
// CTA tile: 64 edges x 256 out, K=512 in 8 chunks of 64.
// 128 threads, 4 warps: warp tile 64m x 64n (wn = wid*64). 2 CTAs per SM
// (128 thr x <=256 regs = half RF; smem 84KB x 2 <= 227KB) so one CTA's
// barrier/cp-wait bubbles are covered by the other CTA's HMMAs.

// dynamic smem layout (bytes):
#define EG_SS       0                      // int[64]
#define EG_ST       256                    // int[64]
#define EG_SB2      1024                   // float[256]
#define EG_SB1      2048                   // float[512]
#define EG_STAGE0   4096                   // A(8192) + B(32768) = 40960 per stage
#define EG_STAGE_SZ 40960
#define EG_B_OFF    8192
#define EG_SMEM_TOTAL (EG_STAGE0 + 2 * EG_STAGE_SZ)   // 86016

__global__ __launch_bounds__(128, 2) void edge_gemm4(const void* __restrict__ ei_raw,
                                                     const float* __restrict__ b1,
                                                     const float* __restrict__ b2,
                                                     float* __restrict__ out, int E) {
    extern __shared__ char smem[];
    uint32_t smem_base = smem_u32(smem);
    int tid = threadIdx.x;
    int wid = tid >> 5, lane = tid & 31;
    int eBase = blockIdx.x * 64;

    int* sS = (int*)(smem + EG_SS);
    int* sT = (int*)(smem + EG_ST);
    float* sb2 = (float*)(smem + EG_SB2);
    float* sb1 = (float*)(smem + EG_SB1);

    // ---- indices + biases ----
    if (tid < 64) {
        int e = eBase + tid;
        int s = 0, t = 0;
        if (e < E) {
            if (g_is64) {
                const long long* ei = (const long long*)ei_raw;
                s = (int)ei[e];
                t = (int)ei[(size_t)E + e];
            } else {
                const int* ei = (const int*)ei_raw;
                s = ei[e];
                t = ei[E + e];
            }
        }
        sS[tid] = min(max(s, 0), NNODES - 1);
        sT[tid] = min(max(t, 0), NNODES - 1);
    }
    sb2[tid] = b2[tid];
    sb2[tid + 128] = b2[tid + 128];
#pragma unroll
    for (int j = 0; j < 4; j++) sb1[tid + j * 128] = b1[tid + j * 128];
    __syncthreads();

    // per-thread A-build job coords: 4 jobs (rows tid>>3 + {0,16,32,48}), group av
    const int av = tid & 7;
    int jS[4], jT[4];
    uint32_t awoff[4];
#pragma unroll
    for (int it = 0; it < 4; it++) {
        int r = (tid >> 3) + it * 16;
        jS[it] = sS[r];
        jT[it] = sT[r];
        awoff[it] = (uint32_t)(r * 128 + ((av ^ (r & 7)) << 4));
    }

    const int wn = wid * 64;              // 4 n-warps, full 64-edge m per warp

    float acc[4][8][4];
#pragma unroll
    for (int a = 0; a < 4; a++)
#pragma unroll
        for (int b = 0; b < 8; b++)
#pragma unroll
            for (int c = 0; c < 4; c++) acc[a][b][c] = 0.f;

    // ---- prologue: chunk 0 into stage 0 ----
    {
        int k = av << 3;
#pragma unroll
        for (int it = 0; it < 4; it++) {
            uint4 ua = *(const uint4*)(g_AB + (size_t)jS[it] * KCAT + k);
            uint4 ub = *(const uint4*)(g_AB + (size_t)jT[it] * KCAT + HID + k);
            const __half* ha = (const __half*)&ua;
            const __half* hb = (const __half*)&ub;
            __half res[8];
#pragma unroll
            for (int j = 0; j < 8; j++) {
                float f = __half2float(ha[j]) + __half2float(hb[j]) + sb1[k + j];
                res[j] = __float2half(fmaxf(f, 0.f));
            }
            *(uint4*)(smem + EG_STAGE0 + awoff[it]) = *(uint4*)res;
        }
#pragma unroll
        for (int jj = 0; jj < 16; jj++) {
            int job = tid + jj * 128;          // 0..2047
            int r = job >> 3, v = job & 7;
            cp_async16(smem_base + EG_STAGE0 + EG_B_OFF + r * 128 + ((v ^ (r & 7)) << 4),
                       g_W2T + (size_t)r * HID + (v << 3));
        }
        cp_commit();
    }

    // ---- mainloop ----
#pragma unroll 1
    for (int ch = 0; ch < 8; ch++) {
        int st = ch & 1;
        cp_wait_all();
        __syncthreads();                          // stage st ready; stage st^1 free
        char* curA = smem + EG_STAGE0 + st * EG_STAGE_SZ;
        char* curB = curA + EG_B_OFF;

        uint4 pa[4], pb[4];
        int kn = 0;
        if (ch < 7) {
            int kc1 = (ch + 1) * 64;
            // B(ch+1) via cp.async into other stage
            uint32_t nb = smem_base + EG_STAGE0 + (st ^ 1) * EG_STAGE_SZ + EG_B_OFF;
#pragma unroll
            for (int jj = 0; jj < 16; jj++) {
                int job = tid + jj * 128;
                int r = job >> 3, v = job & 7;
                cp_async16(nb + r * 128 + ((v ^ (r & 7)) << 4),
                           g_W2T + (size_t)r * HID + kc1 + (v << 3));
            }
            cp_commit();
            // gather loads for A(ch+1) — in flight under the mma loop below
            kn = kc1 + (av << 3);
#pragma unroll
            for (int it = 0; it < 4; it++) {
                pa[it] = *(const uint4*)(g_AB + (size_t)jS[it] * KCAT + kn);
                pb[it] = *(const uint4*)(g_AB + (size_t)jT[it] * KCAT + HID + kn);
            }
        }

        // ---- HMMA on stage st: warp tile 64m x 64n ----
        __half* sA16 = (__half*)curA;
        __half* sB16 = (__half*)curB;
#pragma unroll
        for (int kf = 0; kf < 64; kf += 16) {
            uint32_t a[4][4];
#pragma unroll
            for (int mf = 0; mf < 4; mf++) {
                int rr = mf * 16 + (lane & 15);
                int gl = (kf >> 3) + (lane >> 4);
                ldsm_x4(a[mf], smem_u32(&sA16[rr * 64 + ((gl ^ (rr & 7)) << 3)]));
            }
#pragma unroll
            for (int nf2 = 0; nf2 < 4; nf2++) {
                int rr = wn + nf2 * 16 + ((lane >> 4) << 3) + (lane & 7);
                int gl = (kf >> 3) + ((lane >> 3) & 1);
                uint32_t b[4];
                ldsm_x4(b, smem_u32(&sB16[rr * 64 + ((gl ^ (rr & 7)) << 3)]));
#pragma unroll
                for (int mf = 0; mf < 4; mf++) {
                    mma16816(acc[mf][2 * nf2],     a[mf], b);
                    mma16816(acc[mf][2 * nf2 + 1], a[mf], b + 2);
                }
            }
        }

        if (ch < 7) {
            // finish A(ch+1): relu + cvt + store to other stage
            char* nA = smem + EG_STAGE0 + (st ^ 1) * EG_STAGE_SZ;
#pragma unroll
            for (int it = 0; it < 4; it++) {
                const __half* ha = (const __half*)&pa[it];
                const __half* hb = (const __half*)&pb[it];
                __half res[8];
#pragma unroll
                for (int j = 0; j < 8; j++) {
                    float f = __half2float(ha[j]) + __half2float(hb[j]) + sb1[kn + j];
                    res[j] = __float2half(fmaxf(f, 0.f));
                }
                *(uint4*)(nA + awoff[it]) = *(uint4*)res;
            }
        }
    }

    // ---- epilogue: + b2, fp32 out ----
    int g = lane >> 2, c2 = (lane & 3) << 1;
#pragma unroll
    for (int mf = 0; mf < 4; mf++) {
        int e0 = eBase + mf * 16 + g;
#pragma unroll
        for (int nf = 0; nf < 8; nf++) {
            int n0 = wn + nf * 8 + c2;
            float bx = sb2[n0], by = sb2[n0 + 1];
            if (e0 < E) {
                float2 o = make_float2(acc[mf][nf][0] + bx, acc[mf][nf][1] + by);
                *(float2*)(out + (size_t)e0 * OUTD + n0) = o;
            }
            if (e0 + 8 < E) {
                float2 o = make_float2(acc[mf][nf][2] + bx, acc[mf][nf][3] + by);
                *(float2*)(out + (size_t)(e0 + 8) * OUTD + n0) = o;
            }
        }
    }
}

// ---------------- launch ----------------
extern "C" void kernel_launch(void* const* d_in, const int* in_sizes, int n_in,
                              void* d_out, int out_size) {
    const float* x  = (const float*)d_in[0];
    const void*  ei = d_in[1];
    const float* W1 = (const float*)d_in[2];
    const float* b1 = (const float*)d_in[3];
    const float* W2 = (const float*)d_in[4];
    const float* b2 = (const float*)d_in[5];
    int E = in_sizes[1] / 2;

    cudaFuncSetAttribute(edge_gemm4, cudaFuncAttributeMaxDynamicSharedMemorySize,
                         EG_SMEM_TOTAL);

    detect_kernel<<<1, 256>>>((const int*)ei, in_sizes[1]);
    prep_kernel<<<(NNODES * IND + 255) / 256, 256>>>(x, W1, W2);
    pre_gemm<<<dim3((NNODES + 127) / 128, KCAT / 128), 256>>>();
    edge_gemm4<<<(E + 63) / 64, 128, EG_SMEM_TOTAL>>>(ei, b1, b2, (float*)d_out, E);
}

// round 11
// speedup vs baseline: 1.1963x; 1.0023x over previous
#include <cuda_runtime.h>
#include <cuda_fp16.h>
#include <cstdint>

// Problem dims (fixed by the dataset)
#define NNODES 10000
#define IND    256
#define HID    512
#define OUTD   256
#define KCAT   1024   // A||B concatenated width per node

// ---------------- scratch (no allocations allowed) ----------------
__device__ __half g_x16[NNODES * IND];                 // x in fp16
__device__ __half g_W1catT[KCAT * IND];                // [1024 n][256 k]  K-major
__device__ __half g_W2T[OUTD * HID];                   // [256 n][512 k]   K-major
__device__ __half g_AB[(size_t)NNODES * KCAT];         // per-node A||B, fp16
__device__ int    g_is64;                              // edge_index dtype flag

// ---------------- PTX helpers ----------------
__device__ __forceinline__ uint32_t smem_u32(const void* p) {
    return (uint32_t)__cvta_generic_to_shared(p);
}
__device__ __forceinline__ void ldsm_x4(uint32_t* r, uint32_t addr) {
    asm volatile("ldmatrix.sync.aligned.m8n8.x4.shared.b16 {%0,%1,%2,%3}, [%4];\n"
                 : "=r"(r[0]), "=r"(r[1]), "=r"(r[2]), "=r"(r[3]) : "r"(addr));
}
__device__ __forceinline__ void ldsm_x2(uint32_t* r, uint32_t addr) {
    asm volatile("ldmatrix.sync.aligned.m8n8.x2.shared.b16 {%0,%1}, [%2];\n"
                 : "=r"(r[0]), "=r"(r[1]) : "r"(addr));
}
__device__ __forceinline__ void mma16816(float* d, const uint32_t* a, const uint32_t* b) {
    asm volatile("mma.sync.aligned.m16n8k16.row.col.f32.f16.f16.f32 "
                 "{%0,%1,%2,%3}, {%4,%5,%6,%7}, {%8,%9}, {%0,%1,%2,%3};\n"
                 : "+f"(d[0]), "+f"(d[1]), "+f"(d[2]), "+f"(d[3])
                 : "r"(a[0]), "r"(a[1]), "r"(a[2]), "r"(a[3]), "r"(b[0]), "r"(b[1]));
}
__device__ __forceinline__ void cp_async16(uint32_t smem_addr, const void* gptr) {
    asm volatile("cp.async.ca.shared.global [%0], [%1], 16;\n"
                 :: "r"(smem_addr), "l"(gptr) : "memory");
}
__device__ __forceinline__ void cp_commit() {
    asm volatile("cp.async.commit_group;\n" ::: "memory");
}
__device__ __forceinline__ void cp_wait_all() {
    asm volatile("cp.async.wait_group 0;\n" ::: "memory");
}

// ---------------- prep: fp16 converts + transposes ----------------
__global__ void prep_kernel(const float* __restrict__ x,
                            const float* __restrict__ W1,
                            const float* __restrict__ W2) {
    int i = blockIdx.x * blockDim.x + threadIdx.x;
    if (i < NNODES * IND) g_x16[i] = __float2half(x[i]);
    if (i < KCAT * IND) {
        int j = i / IND, k = i % IND;
        float v = (j < HID) ? W1[(size_t)k * HID + j]
                            : W1[(size_t)(IND + k) * HID + (j - HID)];
        g_W1catT[i] = __float2half(v);
    }
    if (i < OUTD * HID) {
        int n = i / HID, k = i % HID;
        g_W2T[i] = __float2half(W2[(size_t)k * OUTD + n]);
    }
}

// ---------------- detect edge_index dtype (int64 vs int32) ----------------
__global__ void detect_kernel(const int* __restrict__ w, int n_words) {
    __shared__ int nz;
    if (threadIdx.x == 0) nz = 0;
    __syncthreads();
    for (int i = threadIdx.x * 2 + 1; i < n_words; i += 2 * blockDim.x) {
        if (w[i] != 0) { nz = 1; break; }
        if (nz) break;
    }
    __syncthreads();
    if (threadIdx.x == 0) g_is64 = (nz == 0) ? 1 : 0;
}

// ---------------- GEMM1: g_AB = x16 @ W1cat  (M=10000, N=1024, K=256) ----------------
__global__ __launch_bounds__(256) void pre_gemm() {
    __shared__ __half sA[128 * 64];
    __shared__ __half sB[128 * 64];
    int tid = threadIdx.x;
    int mBase = blockIdx.x * 128;
    int nBase = blockIdx.y * 128;
    int wid = tid >> 5, lane = tid & 31;
    int wm = (wid & 3) * 32, wn = (wid >> 2) * 64;

    float acc[2][8][4];
#pragma unroll
    for (int a = 0; a < 2; a++)
#pragma unroll
        for (int b = 0; b < 8; b++)
#pragma unroll
            for (int c = 0; c < 4; c++) acc[a][b][c] = 0.f;

    for (int kc = 0; kc < IND; kc += 64) {
#pragma unroll
        for (int job = tid; job < 128 * 8; job += 256) {
            int r = job >> 3, v = job & 7;
            int m = mBase + r;
            uint4 val = make_uint4(0, 0, 0, 0);
            if (m < NNODES)
                val = *(const uint4*)(g_x16 + (size_t)m * IND + kc + (v << 3));
            *(uint4*)&sA[r * 64 + ((v ^ (r & 7)) << 3)] = val;
        }
#pragma unroll
        for (int job = tid; job < 128 * 8; job += 256) {
            int r = job >> 3, v = job & 7;
            *(uint4*)&sB[r * 64 + ((v ^ (r & 7)) << 3)] =
                *(const uint4*)(g_W1catT + (size_t)(nBase + r) * IND + kc + (v << 3));
        }
        __syncthreads();
#pragma unroll
        for (int kf = 0; kf < 64; kf += 16) {
            uint32_t a[2][4];
#pragma unroll
            for (int mf = 0; mf < 2; mf++) {
                int rr = wm + mf * 16 + (lane & 15);
                int gl = (kf >> 3) + (lane >> 4);
                ldsm_x4(a[mf], smem_u32(&sA[rr * 64 + ((gl ^ (rr & 7)) << 3)]));
            }
#pragma unroll
            for (int nf = 0; nf < 8; nf++) {
                int rr = wn + nf * 8 + (lane & 7);
                int gl = (kf >> 3) + ((lane >> 3) & 1);
                uint32_t b[2];
                ldsm_x2(b, smem_u32(&sB[rr * 64 + ((gl ^ (rr & 7)) << 3)]));
                mma16816(acc[0][nf], a[0], b);
                mma16816(acc[1][nf], a[1], b);
            }
        }
        __syncthreads();
    }
    int g = lane >> 2, c2 = (lane & 3) << 1;
#pragma unroll
    for (int mf = 0; mf < 2; mf++)
#pragma unroll
        for (int nf = 0; nf < 8; nf++) {
            int n0 = nBase + wn + nf * 8 + c2;
            int m0 = mBase + wm + mf * 16 + g;
            if (m0 < NNODES)
                *(half2*)(g_AB + (size_t)m0 * KCAT + n0) =
                    __floats2half2_rn(acc[mf][nf][0], acc[mf][nf][1]);
            if (m0 + 8 < NNODES)
                *(half2*)(g_AB + (size_t)(m0 + 8) * KCAT + n0) =
                    __floats2half2_rn(acc[mf][nf][2], acc[mf][nf][3]);
        }
}

// ---------------- GEMM2: out = relu(A[s]+B[t]+b1) @ W2 + b2 ----------------
// CTA tile: 64 edges x 256 out, K=512 in 8 chunks of 64.
// 128 threads, 4 warps: warp tile 64m x 64n (wn = wid*64). 2 CTAs per SM
// (128 thr x <=256 regs = half RF; smem 84KB x 2 <= 227KB) so one CTA's
// barrier/cp-wait bubbles are covered by the other CTA's HMMAs.

// dynamic smem layout (bytes):
#define EG_SS       0                      // int[64]
#define EG_ST       256                    // int[64]
#define EG_SB2      1024                   // float[256]
#define EG_SB1      2048                   // float[512]
#define EG_STAGE0   4096                   // A(8192) + B(32768) = 40960 per stage
#define EG_STAGE_SZ 40960
#define EG_B_OFF    8192
#define EG_SMEM_TOTAL (EG_STAGE0 + 2 * EG_STAGE_SZ)   // 86016

__global__ __launch_bounds__(128, 2) void edge_gemm4(const void* __restrict__ ei_raw,
                                                     const float* __restrict__ b1,
                                                     const float* __restrict__ b2,
                                                     float* __restrict__ out, int E) {
    extern __shared__ char smem[];
    uint32_t smem_base = smem_u32(smem);
    int tid = threadIdx.x;
    int wid = tid >> 5, lane = tid & 31;
    int eBase = blockIdx.x * 64;

    int* sS = (int*)(smem + EG_SS);
    int* sT = (int*)(smem + EG_ST);
    float* sb2 = (float*)(smem + EG_SB2);
    float* sb1 = (float*)(smem + EG_SB1);

    // ---- indices + biases ----
    if (tid < 64) {
        int e = eBase + tid;
        int s = 0, t = 0;
        if (e < E) {
            if (g_is64) {
                const long long* ei = (const long long*)ei_raw;
                s = (int)ei[e];
                t = (int)ei[(size_t)E + e];
            } else {
                const int* ei = (const int*)ei_raw;
                s = ei[e];
                t = ei[E + e];
            }
        }
        sS[tid] = min(max(s, 0), NNODES - 1);
        sT[tid] = min(max(t, 0), NNODES - 1);
    }
    sb2[tid] = b2[tid];
    sb2[tid + 128] = b2[tid + 128];
#pragma unroll
    for (int j = 0; j < 4; j++) sb1[tid + j * 128] = b1[tid + j * 128];
    __syncthreads();

    // per-thread A-build job coords: 4 jobs (rows tid>>3 + {0,16,32,48}), group av
    const int av = tid & 7;
    int jS[4], jT[4];
    uint32_t awoff[4];
#pragma unroll
    for (int it = 0; it < 4; it++) {
        int r = (tid >> 3) + it * 16;
        jS[it] = sS[r];
        jT[it] = sT[r];
        awoff[it] = (uint32_t)(r * 128 + ((av ^ (r & 7)) << 4));
    }

    const int wn = wid * 64;              // 4 n-warps, full 64-edge m per warp

    float acc[4][8][4];
#pragma unroll
    for (int a = 0; a < 4; a++)
#pragma unroll
        for (int b = 0; b < 8; b++)
#pragma unroll
            for (int c = 0; c < 4; c++) acc[a][b][c] = 0.f;

    // ---- prologue: chunk 0 into stage 0 ----
    {
        int k = av << 3;
#pragma unroll
        for (int it = 0; it < 4; it++) {
            uint4 ua = *(const uint4*)(g_AB + (size_t)jS[it] * KCAT + k);
            uint4 ub = *(const uint4*)(g_AB + (size_t)jT[it] * KCAT + HID + k);
            const __half* ha = (const __half*)&ua;
            const __half* hb = (const __half*)&ub;
            __half res[8];
#pragma unroll
            for (int j = 0; j < 8; j++) {
                float f = __half2float(ha[j]) + __half2float(hb[j]) + sb1[k + j];
                res[j] = __float2half(fmaxf(f, 0.f));
            }
            *(uint4*)(smem + EG_STAGE0 + awoff[it]) = *(uint4*)res;
        }
#pragma unroll
        for (int jj = 0; jj < 16; jj++) {
            int job = tid + jj * 128;          // 0..2047
            int r = job >> 3, v = job & 7;
            cp_async16(smem_base + EG_STAGE0 + EG_B_OFF + r * 128 + ((v ^ (r & 7)) << 4),
                       g_W2T + (size_t)r * HID + (v << 3));
        }
        cp_commit();
    }

    // ---- mainloop ----
#pragma unroll 1
    for (int ch = 0; ch < 8; ch++) {
        int st = ch & 1;
        cp_wait_all();
        __syncthreads();                          // stage st ready; stage st^1 free
        char* curA = smem + EG_STAGE0 + st * EG_STAGE_SZ;
        char* curB = curA + EG_B_OFF;

        uint4 pa[4], pb[4];
        int kn = 0;
        if (ch < 7) {
            int kc1 = (ch + 1) * 64;
            // B(ch+1) via cp.async into other stage
            uint32_t nb = smem_base + EG_STAGE0 + (st ^ 1) * EG_STAGE_SZ + EG_B_OFF;
#pragma unroll
            for (int jj = 0; jj < 16; jj++) {
                int job = tid + jj * 128;
                int r = job >> 3, v = job & 7;
                cp_async16(nb + r * 128 + ((v ^ (r & 7)) << 4),
                           g_W2T + (size_t)r * HID + kc1 + (v << 3));
            }
            cp_commit();
            // gather loads for A(ch+1) — in flight under the mma loop below
            kn = kc1 + (av << 3);
#pragma unroll
            for (int it = 0; it < 4; it++) {
                pa[it] = *(const uint4*)(g_AB + (size_t)jS[it] * KCAT + kn);
                pb[it] = *(const uint4*)(g_AB + (size_t)jT[it] * KCAT + HID + kn);
            }
        }

        // ---- HMMA on stage st: warp tile 64m x 64n ----
        __half* sA16 = (__half*)curA;
        __half* sB16 = (__half*)curB;
#pragma unroll
        for (int kf = 0; kf < 64; kf += 16) {
            uint32_t a[4][4];
#pragma unroll
            for (int mf = 0; mf < 4; mf++) {
                int rr = mf * 16 + (lane & 15);
                int gl = (kf >> 3) + (lane >> 4);
                ldsm_x4(a[mf], smem_u32(&sA16[rr * 64 + ((gl ^ (rr & 7)) << 3)]));
            }
#pragma unroll
            for (int nf2 = 0; nf2 < 4; nf2++) {
                int rr = wn + nf2 * 16 + ((lane >> 4) << 3) + (lane & 7);
                int gl = (kf >> 3) + ((lane >> 3) & 1);
                uint32_t b[4];
                ldsm_x4(b, smem_u32(&sB16[rr * 64 + ((gl ^ (rr & 7)) << 3)]));
#pragma unroll
                for (int mf = 0; mf < 4; mf++) {
                    mma16816(acc[mf][2 * nf2],     a[mf], b);
                    mma16816(acc[mf][2 * nf2 + 1], a[mf], b + 2);
                }
            }
        }

        if (ch < 7) {
            // finish A(ch+1): relu + cvt + store to other stage
            char* nA = smem + EG_STAGE0 + (st ^ 1) * EG_STAGE_SZ;
#pragma unroll
            for (int it = 0; it < 4; it++) {
                const __half* ha = (const __half*)&pa[it];
                const __half* hb = (const __half*)&pb[it];
                __half res[8];
#pragma unroll
                for (int j = 0; j < 8; j++) {
                    float f = __half2float(ha[j]) + __half2float(hb[j]) + sb1[kn + j];
                    res[j] = __float2half(fmaxf(f, 0.f));
                }
                *(uint4*)(nA + awoff[it]) = *(uint4*)res;
            }
        }
    }

    // ---- epilogue: + b2, fp32 out ----
    int g = lane >> 2, c2 = (lane & 3) << 1;
#pragma unroll
    for (int mf = 0; mf < 4; mf++) {
        int e0 = eBase + mf * 16 + g;
#pragma unroll
        for (int nf = 0; nf < 8; nf++) {
            int n0 = wn + nf * 8 + c2;
            float bx = sb2[n0], by = sb2[n0 + 1];
            if (e0 < E) {
                float2 o = make_float2(acc[mf][nf][0] + bx, acc[mf][nf][1] + by);
                *(float2*)(out + (size_t)e0 * OUTD + n0) = o;
            }
            if (e0 + 8 < E) {
                float2 o = make_float2(acc[mf][nf][2] + bx, acc[mf][nf][3] + by);
                *(float2*)(out + (size_t)(e0 + 8) * OUTD + n0) = o;
            }
        }
    }
}

// ---------------- launch ----------------
extern "C" void kernel_launch(void* const* d_in, const int* in_sizes, int n_in,
                              void* d_out, int out_size) {
    const float* x  = (const float*)d_in[0];
    const void*  ei = d_in[1];
    const float* W1 = (const float*)d_in[2];
    const float* b1 = (const float*)d_in[3];
    const float* W2 = (const float*)d_in[4];
    const float* b2 = (const float*)d_in[5];
    int E = in_sizes[1] / 2;

    cudaFuncSetAttribute(edge_gemm4, cudaFuncAttributeMaxDynamicSharedMemorySize,
                         EG_SMEM_TOTAL);

    detect_kernel<<<1, 256>>>((const int*)ei, in_sizes[1]);
    prep_kernel<<<(NNODES * IND + 255) / 256, 256>>>(x, W1, W2);
    pre_gemm<<<dim3((NNODES + 127) / 128, KCAT / 128), 256>>>();
    edge_gemm4<<<(E + 63) / 64, 128, EG_SMEM_TOTAL>>>(ei, b1, b2, (float*)d_out, E);
}